// round 15
// baseline (speedup 1.0000x reference)
#include <cuda_runtime.h>
#include <cstdint>
#include <cstddef>

// BS=8, H=16, NUM_JOB=64, OPS_PER_JOB=32, DK=64, L=2048.
// op_mapping == [1]*32+[0]*32 per job => 8192 independent 32-token causal
// attention windows, RoPE positions 0..31, scale 1/8.
//
// TWO warps per window (block=64): warp w owns output rows 16w..16w+15.
// Causality: warp0's rows only attend keys 0..15 => NT=2 key-tiles; warp1 NT=4.
// Zero smem. mma.m16n8k8 tf32, 3-pass split (fp32-grade accuracy).
// QK k-permutation: per 16-col double-tile, thread t owns data cols 4t..4t+3
//   (float4 loads for Q/K and the rope table).
// WV k-permutation: slot t -> key 2t, t+4 -> 2t+1, so the softmaxed QK C-frag
//   IS W's A-fragment (order c0,c2,c1,c3).

__device__ float2 g_rope2[32 * 32];   // [row][j] = (cos,sin) for col pair 2j,2j+1

__global__ void rope_init_kernel() {
    int tdx = blockIdx.x * 32 + threadIdx.x;   // 0..1023
    int row = tdx >> 5;
    int j   = tdx & 31;                        // pair index
    const double ln1e4_over32 = 9.210340371976184 / 32.0;
    double th = exp(-(double)j * ln1e4_over32);   // theta_j = 10000^(-j/32)
    double s, c;
    sincos((double)row * th, &s, &c);
    g_rope2[tdx] = make_float2((float)c, (float)s);
}

__device__ __forceinline__ void split_tf32(float x, uint32_t &hi, uint32_t &lo) {
    float b;
    asm("cvt.rna.tf32.f32 %0, %1;" : "=f"(b) : "f"(x));
    hi = __float_as_uint(b);
    lo = __float_as_uint(x - b);
}

__device__ __forceinline__ void mma_tf32(float c[4], uint32_t a0, uint32_t a1,
                                         uint32_t a2, uint32_t a3,
                                         uint32_t b0, uint32_t b1) {
    asm("mma.sync.aligned.m16n8k8.row.col.f32.tf32.tf32.f32 "
        "{%0,%1,%2,%3}, {%4,%5,%6,%7}, {%8,%9}, {%0,%1,%2,%3};"
        : "+f"(c[0]), "+f"(c[1]), "+f"(c[2]), "+f"(c[3])
        : "r"(a0), "r"(a1), "r"(a2), "r"(a3), "r"(b0), "r"(b1));
}

// One warp computes output rows [mrow, mrow+16) of its window, attending
// keys [0, 8*NT). Requires mrow+16 <= 8*NT (causal coverage).
template <int NT>
__device__ __forceinline__ void attn_warp(const float* __restrict__ Qb,
                                          const float* __restrict__ Kb,
                                          const float* __restrict__ Vb,
                                          float* __restrict__ ob,
                                          uint32_t g, uint32_t t, uint32_t mrow) {
    const float4* rope4 = (const float4*)g_rope2;   // [row*16 + slot]

    // ---------------- QK^T : rows mrow..mrow+15, keys 0..8NT-1 ------------
    float C[NT][4];
#pragma unroll
    for (int nt = 0; nt < NT; nt++)
#pragma unroll
        for (int j = 0; j < 4; j++) C[nt][j] = 0.f;

#pragma unroll
    for (int ktp = 0; ktp < 4; ktp++) {
        const uint32_t c0 = ktp * 16u + 4u * t;   // this thread's 4 data cols
        const uint32_t ri = ktp * 4u + t;         // rope float4 slot

        const uint32_t r0 = mrow + g;
        const uint32_t r1 = r0 + 8u;
        float4 x0 = *(const float4*)(Qb + r0 * 64u + c0);
        float4 x1 = *(const float4*)(Qb + r1 * 64u + c0);
        float4 t0 = rope4[r0 * 16u + ri];
        float4 t1 = rope4[r1 * 16u + ri];
        float yq[2][4];
        yq[0][0] = (x0.x * t0.x - x0.y * t0.y) * 0.125f;
        yq[0][1] = (x0.y * t0.x + x0.x * t0.y) * 0.125f;
        yq[0][2] = (x0.z * t0.z - x0.w * t0.w) * 0.125f;
        yq[0][3] = (x0.w * t0.z + x0.z * t0.w) * 0.125f;
        yq[1][0] = (x1.x * t1.x - x1.y * t1.y) * 0.125f;
        yq[1][1] = (x1.y * t1.x + x1.x * t1.y) * 0.125f;
        yq[1][2] = (x1.z * t1.z - x1.w * t1.w) * 0.125f;
        yq[1][3] = (x1.w * t1.z + x1.z * t1.w) * 0.125f;

        float yk[NT][4];
#pragma unroll
        for (int nt = 0; nt < NT; nt++) {
            const uint32_t r = (uint32_t)nt * 8u + g;
            float4 x  = *(const float4*)(Kb + r * 64u + c0);
            float4 tt = rope4[r * 16u + ri];
            yk[nt][0] = x.x * tt.x - x.y * tt.y;
            yk[nt][1] = x.y * tt.x + x.x * tt.y;
            yk[nt][2] = x.z * tt.z - x.w * tt.w;
            yk[nt][3] = x.w * tt.z + x.z * tt.w;
        }

#pragma unroll
        for (int sub = 0; sub < 2; sub++) {
            uint32_t Ah[4], Al[4];
            split_tf32(yq[0][2 * sub],     Ah[0], Al[0]);
            split_tf32(yq[1][2 * sub],     Ah[1], Al[1]);
            split_tf32(yq[0][2 * sub + 1], Ah[2], Al[2]);
            split_tf32(yq[1][2 * sub + 1], Ah[3], Al[3]);
#pragma unroll
            for (int nt = 0; nt < NT; nt++) {
                uint32_t Bh0, Bl0, Bh1, Bl1;
                split_tf32(yk[nt][2 * sub],     Bh0, Bl0);
                split_tf32(yk[nt][2 * sub + 1], Bh1, Bl1);
                mma_tf32(C[nt], Ah[0], Ah[1], Ah[2], Ah[3], Bh0, Bh1);
                mma_tf32(C[nt], Al[0], Al[1], Al[2], Al[3], Bh0, Bh1);
                mma_tf32(C[nt], Ah[0], Ah[1], Ah[2], Ah[3], Bl0, Bl1);
            }
        }
    }

    // ---------------- causal softmax on C fragments -----------------------
    // c0=(rA, 8nt+2t) c1=(rA,+1) c2=(rB, 2t) c3=(rB,+1); rA=mrow+g, rB=rA+8.
    {
        const int rA = (int)(mrow + g);
        const int rB = rA + 8;
        float mxA = -1e30f, mxB = -1e30f;
#pragma unroll
        for (int nt = 0; nt < NT; nt++) {
            const int cc = 8 * nt + 2 * (int)t;
            if (cc     > rA) C[nt][0] = -1e30f;
            if (cc + 1 > rA) C[nt][1] = -1e30f;
            if (cc     > rB) C[nt][2] = -1e30f;
            if (cc + 1 > rB) C[nt][3] = -1e30f;
            mxA = fmaxf(mxA, fmaxf(C[nt][0], C[nt][1]));
            mxB = fmaxf(mxB, fmaxf(C[nt][2], C[nt][3]));
        }
        mxA = fmaxf(mxA, __shfl_xor_sync(0xffffffffu, mxA, 1));
        mxA = fmaxf(mxA, __shfl_xor_sync(0xffffffffu, mxA, 2));
        mxB = fmaxf(mxB, __shfl_xor_sync(0xffffffffu, mxB, 1));
        mxB = fmaxf(mxB, __shfl_xor_sync(0xffffffffu, mxB, 2));
        float sA = 0.f, sB = 0.f;
#pragma unroll
        for (int nt = 0; nt < NT; nt++) {
            C[nt][0] = __expf(C[nt][0] - mxA); sA += C[nt][0];
            C[nt][1] = __expf(C[nt][1] - mxA); sA += C[nt][1];
            C[nt][2] = __expf(C[nt][2] - mxB); sB += C[nt][2];
            C[nt][3] = __expf(C[nt][3] - mxB); sB += C[nt][3];
        }
        sA += __shfl_xor_sync(0xffffffffu, sA, 1);
        sA += __shfl_xor_sync(0xffffffffu, sA, 2);
        sB += __shfl_xor_sync(0xffffffffu, sB, 1);
        sB += __shfl_xor_sync(0xffffffffu, sB, 2);
        const float iA = 1.0f / sA;
        const float iB = 1.0f / sB;
#pragma unroll
        for (int nt = 0; nt < NT; nt++) {
            C[nt][0] *= iA;
            C[nt][1] *= iA;
            C[nt][2] *= iB;
            C[nt][3] *= iB;
        }
    }

    // ---------------- O = W V ; W A-frags == C frags (c0,c2,c1,c3) --------
#pragma unroll
    for (int half = 0; half < 2; half++) {
        float Cw[4][4];
#pragma unroll
        for (int nti = 0; nti < 4; nti++)
#pragma unroll
            for (int j = 0; j < 4; j++) Cw[nti][j] = 0.f;

#pragma unroll
        for (int kt = 0; kt < NT; kt++) {        // keys 8kt..8kt+7
            uint32_t Wh[4], Wl[4];
            split_tf32(C[kt][0], Wh[0], Wl[0]);
            split_tf32(C[kt][2], Wh[1], Wl[1]);
            split_tf32(C[kt][1], Wh[2], Wl[2]);
            split_tf32(C[kt][3], Wh[3], Wl[3]);
            const uint32_t p0 = (uint32_t)kt * 8u + 2u * t;   // permuted key rows
            const float* vr0 = Vb + p0 * 64u;
            const float* vr1 = vr0 + 64u;
#pragma unroll
            for (int nti = 0; nti < 4; nti++) {
                const uint32_t ncol = (uint32_t)(half * 4 + nti) * 8u + g;
                uint32_t b0h, b0l, b1h, b1l;
                split_tf32(vr0[ncol], b0h, b0l);
                split_tf32(vr1[ncol], b1h, b1l);
                mma_tf32(Cw[nti], Wh[0], Wh[1], Wh[2], Wh[3], b0h, b1h);
                mma_tf32(Cw[nti], Wl[0], Wl[1], Wl[2], Wl[3], b0h, b1h);
                mma_tf32(Cw[nti], Wh[0], Wh[1], Wh[2], Wh[3], b0l, b1l);
            }
        }

        const uint32_t rA = mrow + g;
#pragma unroll
        for (int nti = 0; nti < 4; nti++) {
            float* pA = ob + rA * 1024u + (uint32_t)(half * 4 + nti) * 8u + 2u * t;
            float* pB = pA + 8u * 1024u;
            *(float2*)pA = make_float2(Cw[nti][0], Cw[nti][1]);
            *(float2*)pB = make_float2(Cw[nti][2], Cw[nti][3]);
        }
    }
}

__global__ __launch_bounds__(64, 12)
void win_attn_kernel(const float* __restrict__ q,
                     const float* __restrict__ k,
                     const float* __restrict__ v,
                     float* __restrict__ out) {
    const uint32_t wid  = threadIdx.x >> 5;
    const uint32_t lane = threadIdx.x & 31u;
    const uint32_t g = lane >> 2;
    const uint32_t t = lane & 3u;
    const uint32_t job = blockIdx.x;            // 0..8191
    const uint32_t bh = job >> 6;               // b*16 + h
    const uint32_t jb = job & 63u;

    const uint32_t base = bh * (2048u * 64u) + jb * (32u * 64u);
    const float* Qb = q + base;
    const float* Kb = k + base;
    const float* Vb = v + base;

    // out offset = (b*2048 + jb*32)*1024 + h*64
    float* ob = out + (bh >> 4) * (2048u * 1024u) + jb * (32u * 1024u)
                    + (bh & 15u) * 64u;

    // Warm L2 for V (consumed last). Warp0 needs rows 0-15, warp1 all 32.
    {
        const char* vp = (const char*)Vb + (wid * 32u + lane) * 128u;
        asm volatile("prefetch.global.L2 [%0];" :: "l"(vp));
    }

    if (wid == 0) {
        attn_warp<2>(Qb, Kb, Vb, ob, g, t, 0u);    // rows 0-15, keys 0-15
    } else {
        attn_warp<4>(Qb, Kb, Vb, ob, g, t, 16u);   // rows 16-31, keys 0-31
    }
}

extern "C" void kernel_launch(void* const* d_in, const int* in_sizes, int n_in,
                              void* d_out, int out_size) {
    const float* q = (const float*)d_in[0];
    const float* k = (const float*)d_in[1];
    const float* v = (const float*)d_in[2];
    float* out = (float*)d_out;

    rope_init_kernel<<<32, 32>>>();
    win_attn_kernel<<<8 * 16 * 64, 64>>>(q, k, v, out);
}

// round 16
// speedup vs baseline: 1.0420x; 1.0420x over previous
#include <cuda_runtime.h>
#include <cstdint>
#include <cstddef>

// BS=8, H=16, NUM_JOB=64, OPS_PER_JOB=32, DK=64, L=2048.
// op_mapping == [1]*32+[0]*32 per job => 8192 independent 32-token causal
// attention windows, RoPE positions 0..31, scale 1/8.
//
// One warp per window. mma.m16n8k8 tf32, 3-pass split (fp32-grade accuracy).
// V is copied GMEM->SMEM via cp.async at warp start (overlaps all of QK),
// then read with conflict-free LDS (row pitch 68 floats).
// QK k-permutation: per 16-col double-tile, thread t owns data cols 4t..4t+3
//   (float4 loads for Q/K and rope). Rope rows for Q == rope rows for K
//   ({g, g+8, g+16, g+24}) -> 4 table loads per ktp serve both.
// WV k-permutation: slot t -> key 2t, t+4 -> 2t+1, so the softmaxed QK C-frag
//   IS W's A-fragment (order c0,c2,c1,c3).

#define VP 68   // smem V row pitch (floats): bank = (4*row + col) % 32

__device__ float2 g_rope2[32 * 32];   // [row][j] = (cos,sin) for col pair 2j,2j+1

__global__ void rope_init_kernel() {
    int tdx = blockIdx.x * 32 + threadIdx.x;   // 0..1023
    int row = tdx >> 5;
    int j   = tdx & 31;                        // pair index
    const double ln1e4_over32 = 9.210340371976184 / 32.0;
    double th = exp(-(double)j * ln1e4_over32);   // theta_j = 10000^(-j/32)
    double s, c;
    sincos((double)row * th, &s, &c);
    g_rope2[tdx] = make_float2((float)c, (float)s);
}

__device__ __forceinline__ void split_tf32(float x, uint32_t &hi, uint32_t &lo) {
    float b;
    asm("cvt.rna.tf32.f32 %0, %1;" : "=f"(b) : "f"(x));
    hi = __float_as_uint(b);
    lo = __float_as_uint(x - b);
}

__device__ __forceinline__ void mma_tf32(float c[4], uint32_t a0, uint32_t a1,
                                         uint32_t a2, uint32_t a3,
                                         uint32_t b0, uint32_t b1) {
    asm("mma.sync.aligned.m16n8k8.row.col.f32.tf32.tf32.f32 "
        "{%0,%1,%2,%3}, {%4,%5,%6,%7}, {%8,%9}, {%0,%1,%2,%3};"
        : "+f"(c[0]), "+f"(c[1]), "+f"(c[2]), "+f"(c[3])
        : "r"(a0), "r"(a1), "r"(a2), "r"(a3), "r"(b0), "r"(b1));
}

__global__ __launch_bounds__(32, 18)
void win_attn_kernel(const float* __restrict__ q,
                     const float* __restrict__ k,
                     const float* __restrict__ v,
                     float* __restrict__ out) {
    __shared__ __align__(16) float sV[32 * VP];   // 8704 B

    const uint32_t lane = threadIdx.x;
    const uint32_t g = lane >> 2;    // fragment group 0..7
    const uint32_t t = lane & 3u;    // thread-in-group 0..3
    const uint32_t job = blockIdx.x;            // 0..8191
    const uint32_t bh = job >> 6;               // b*16 + h
    const uint32_t jb = job & 63u;

    const uint32_t base = bh * (2048u * 64u) + jb * (32u * 64u);
    const float* Qb = q + base;
    const float* Kb = k + base;
    const float* Vb = v + base;

    // ---- kick off V GMEM->SMEM (completes during QK/softmax) ----
    {
        uint32_t sv;
        asm("{ .reg .u64 a; cvta.to.shared.u64 a, %1; cvt.u32.u64 %0, a; }"
            : "=r"(sv) : "l"(sV));
#pragma unroll
        for (int i = 0; i < 16; i++) {
            const uint32_t f = (uint32_t)i * 32u + lane;   // float4 index
            const uint32_t r = f >> 4, c4 = f & 15u;
            const float* src = Vb + r * 64u + c4 * 4u;
            uint32_t dst = sv + (r * VP + c4 * 4u) * 4u;
            asm volatile("cp.async.cg.shared.global [%0], [%1], 16;"
                         :: "r"(dst), "l"(src));
        }
        asm volatile("cp.async.commit_group;");
    }

    const float4* rope4 = (const float4*)g_rope2;   // [row*16 + slot]

    // ================= QK^T : S[32][32], 2 m-tiles x 4 n-tiles =============
    float C[2][4][4];
#pragma unroll
    for (int m = 0; m < 2; m++)
#pragma unroll
        for (int nt = 0; nt < 4; nt++)
#pragma unroll
            for (int j = 0; j < 4; j++) C[m][nt][j] = 0.f;

#pragma unroll
    for (int ktp = 0; ktp < 4; ktp++) {
        const uint32_t c0 = (uint32_t)ktp * 16u + 4u * t;  // 4 data cols
        const uint32_t ri = (uint32_t)ktp * 4u + t;        // rope slot

        // Rope rows {g, g+8, g+16, g+24} serve BOTH Q and K.
        float4 tt[4];
#pragma unroll
        for (int i = 0; i < 4; i++)
            tt[i] = rope4[((uint32_t)i * 8u + g) * 16u + ri];

        // ---- rotated Q (RoPE + 0.125): rows m16+g (tt[2m]), +8 (tt[2m+1])
        float yq[2][2][4];
#pragma unroll
        for (int m = 0; m < 2; m++) {
            const uint32_t r0 = (uint32_t)m * 16u + g;
            float4 x0 = *(const float4*)(Qb + r0 * 64u + c0);
            float4 x1 = *(const float4*)(Qb + (r0 + 8u) * 64u + c0);
            float4 t0 = tt[2 * m];
            float4 t1 = tt[2 * m + 1];
            yq[m][0][0] = (x0.x * t0.x - x0.y * t0.y) * 0.125f;
            yq[m][0][1] = (x0.y * t0.x + x0.x * t0.y) * 0.125f;
            yq[m][0][2] = (x0.z * t0.z - x0.w * t0.w) * 0.125f;
            yq[m][0][3] = (x0.w * t0.z + x0.z * t0.w) * 0.125f;
            yq[m][1][0] = (x1.x * t1.x - x1.y * t1.y) * 0.125f;
            yq[m][1][1] = (x1.y * t1.x + x1.x * t1.y) * 0.125f;
            yq[m][1][2] = (x1.z * t1.z - x1.w * t1.w) * 0.125f;
            yq[m][1][3] = (x1.w * t1.z + x1.z * t1.w) * 0.125f;
        }
        // ---- rotated K: rows nt8+g, rope tt[nt] ----
        float yk[4][4];
#pragma unroll
        for (int nt = 0; nt < 4; nt++) {
            const uint32_t r = (uint32_t)nt * 8u + g;
            float4 x = *(const float4*)(Kb + r * 64u + c0);
            float4 tr = tt[nt];
            yk[nt][0] = x.x * tr.x - x.y * tr.y;
            yk[nt][1] = x.y * tr.x + x.x * tr.y;
            yk[nt][2] = x.z * tr.z - x.w * tr.w;
            yk[nt][3] = x.w * tr.z + x.z * tr.w;
        }

        // ---- two k8 tiles: sub=0 -> cols 4t,4t+1; sub=1 -> 4t+2,4t+3 ----
#pragma unroll
        for (int sub = 0; sub < 2; sub++) {
            uint32_t Ah[2][4], Al[2][4];
#pragma unroll
            for (int m = 0; m < 2; m++) {
                split_tf32(yq[m][0][2 * sub],     Ah[m][0], Al[m][0]);
                split_tf32(yq[m][1][2 * sub],     Ah[m][1], Al[m][1]);
                split_tf32(yq[m][0][2 * sub + 1], Ah[m][2], Al[m][2]);
                split_tf32(yq[m][1][2 * sub + 1], Ah[m][3], Al[m][3]);
            }
#pragma unroll
            for (int nt = 0; nt < 4; nt++) {
                uint32_t Bh0, Bl0, Bh1, Bl1;
                split_tf32(yk[nt][2 * sub],     Bh0, Bl0);
                split_tf32(yk[nt][2 * sub + 1], Bh1, Bl1);
#pragma unroll
                for (int m = 0; m < 2; m++) {
                    mma_tf32(C[m][nt], Ah[m][0], Ah[m][1], Ah[m][2], Ah[m][3],
                             Bh0, Bh1);
                    mma_tf32(C[m][nt], Al[m][0], Al[m][1], Al[m][2], Al[m][3],
                             Bh0, Bh1);
                    mma_tf32(C[m][nt], Ah[m][0], Ah[m][1], Ah[m][2], Ah[m][3],
                             Bl0, Bl1);
                }
            }
        }
    }

    // ================= causal softmax on C fragments ========================
    // c0=(rA, 8nt+2t) c1=(rA,+1) c2=(rB,2t) c3=(rB,+1); rA=m16+g, rB=rA+8.
#pragma unroll
    for (int m = 0; m < 2; m++) {
        const int rA = m * 16 + (int)g;
        const int rB = rA + 8;
        float mxA = -1e30f, mxB = -1e30f;
#pragma unroll
        for (int nt = 0; nt < 4; nt++) {
            const int cc = 8 * nt + 2 * (int)t;
            if (cc     > rA) C[m][nt][0] = -1e30f;
            if (cc + 1 > rA) C[m][nt][1] = -1e30f;
            if (cc     > rB) C[m][nt][2] = -1e30f;
            if (cc + 1 > rB) C[m][nt][3] = -1e30f;
            mxA = fmaxf(mxA, fmaxf(C[m][nt][0], C[m][nt][1]));
            mxB = fmaxf(mxB, fmaxf(C[m][nt][2], C[m][nt][3]));
        }
        mxA = fmaxf(mxA, __shfl_xor_sync(0xffffffffu, mxA, 1));
        mxA = fmaxf(mxA, __shfl_xor_sync(0xffffffffu, mxA, 2));
        mxB = fmaxf(mxB, __shfl_xor_sync(0xffffffffu, mxB, 1));
        mxB = fmaxf(mxB, __shfl_xor_sync(0xffffffffu, mxB, 2));
        float sA = 0.f, sB = 0.f;
#pragma unroll
        for (int nt = 0; nt < 4; nt++) {
            C[m][nt][0] = __expf(C[m][nt][0] - mxA); sA += C[m][nt][0];
            C[m][nt][1] = __expf(C[m][nt][1] - mxA); sA += C[m][nt][1];
            C[m][nt][2] = __expf(C[m][nt][2] - mxB); sB += C[m][nt][2];
            C[m][nt][3] = __expf(C[m][nt][3] - mxB); sB += C[m][nt][3];
        }
        sA += __shfl_xor_sync(0xffffffffu, sA, 1);
        sA += __shfl_xor_sync(0xffffffffu, sA, 2);
        sB += __shfl_xor_sync(0xffffffffu, sB, 1);
        sB += __shfl_xor_sync(0xffffffffu, sB, 2);
        const float iA = 1.0f / sA;
        const float iB = 1.0f / sB;
#pragma unroll
        for (int nt = 0; nt < 4; nt++) {
            C[m][nt][0] *= iA;
            C[m][nt][1] *= iA;
            C[m][nt][2] *= iB;
            C[m][nt][3] *= iB;
        }
    }

    // ---- V must be in smem now (overlapped with all of the above) ----
    asm volatile("cp.async.wait_group 0;");
    __syncthreads();

    // ================= O = W V ; W A-frags == C frags (c0,c2,c1,c3) ========
    // out offset = (b*2048 + jb*32)*1024 + h*64
    float* ob = out + (bh >> 4) * (2048u * 1024u) + jb * (32u * 1024u)
                    + (bh & 15u) * 64u;
#pragma unroll
    for (int half = 0; half < 2; half++) {
        float Cw[2][4][4];
#pragma unroll
        for (int m = 0; m < 2; m++)
#pragma unroll
            for (int nti = 0; nti < 4; nti++)
#pragma unroll
                for (int j = 0; j < 4; j++) Cw[m][nti][j] = 0.f;

#pragma unroll
        for (int kt = 0; kt < 4; kt++) {
            uint32_t Wh[2][4], Wl[2][4];
#pragma unroll
            for (int m = 0; m < 2; m++) {
                split_tf32(C[m][kt][0], Wh[m][0], Wl[m][0]);
                split_tf32(C[m][kt][2], Wh[m][1], Wl[m][1]);
                split_tf32(C[m][kt][1], Wh[m][2], Wl[m][2]);
                split_tf32(C[m][kt][3], Wh[m][3], Wl[m][3]);
            }
            const uint32_t p0 = (uint32_t)kt * 8u + 2u * t;   // permuted key rows
            const float* vr0 = &sV[p0 * VP];
            const float* vr1 = vr0 + VP;
#pragma unroll
            for (int nti = 0; nti < 4; nti++) {
                const uint32_t ncol = (uint32_t)(half * 4 + nti) * 8u + g;
                uint32_t b0h, b0l, b1h, b1l;
                split_tf32(vr0[ncol], b0h, b0l);
                split_tf32(vr1[ncol], b1h, b1l);
#pragma unroll
                for (int m = 0; m < 2; m++) {
                    mma_tf32(Cw[m][nti], Wh[m][0], Wh[m][1], Wh[m][2], Wh[m][3],
                             b0h, b1h);
                    mma_tf32(Cw[m][nti], Wl[m][0], Wl[m][1], Wl[m][2], Wl[m][3],
                             b0h, b1h);
                    mma_tf32(Cw[m][nti], Wh[m][0], Wh[m][1], Wh[m][2], Wh[m][3],
                             b0l, b1l);
                }
            }
        }

        // stores: rows m16+g / +8, cols (half*4+nti)*8 + 2t (+1)
#pragma unroll
        for (int m = 0; m < 2; m++) {
            const uint32_t rA = (uint32_t)m * 16u + g;
#pragma unroll
            for (int nti = 0; nti < 4; nti++) {
                float* pA = ob + rA * 1024u
                               + (uint32_t)(half * 4 + nti) * 8u + 2u * t;
                float* pB = pA + 8u * 1024u;
                *(float2*)pA = make_float2(Cw[m][nti][0], Cw[m][nti][1]);
                *(float2*)pB = make_float2(Cw[m][nti][2], Cw[m][nti][3]);
            }
        }
    }
}

extern "C" void kernel_launch(void* const* d_in, const int* in_sizes, int n_in,
                              void* d_out, int out_size) {
    const float* q = (const float*)d_in[0];
    const float* k = (const float*)d_in[1];
    const float* v = (const float*)d_in[2];
    float* out = (float*)d_out;

    rope_init_kernel<<<32, 32>>>();
    win_attn_kernel<<<8 * 16 * 64, 32>>>(q, k, v, out);
}

// round 17
// speedup vs baseline: 1.0988x; 1.0545x over previous
#include <cuda_runtime.h>
#include <cstdint>
#include <cstddef>

// BS=8, H=16, NUM_JOB=64, OPS_PER_JOB=32, DK=64, L=2048.
// op_mapping == [1]*32+[0]*32 per job => 8192 independent 32-token causal
// attention windows, RoPE positions 0..31, scale 1/8.
//
// One warp per window. mma.m16n8k8 tf32, 3-pass split (fp32-grade accuracy).
// Causal tile pruning: rows 0-15 (m=0) never see keys 16-31, so QK tiles
// (m0,nt2/3) and WV tiles (m0,kt2/3) are skipped entirely (-25% MMAs).
// V is copied GMEM->SMEM via cp.async at warp start (overlaps all of QK),
// then read with conflict-free LDS (row pitch 68 floats).
// QK k-permutation: per 16-col double-tile, thread t owns data cols 4t..4t+3
//   (float4 loads for Q/K and rope; rope rows shared between Q and K).
// WV k-permutation: slot t -> key 2t, t+4 -> 2t+1, so the softmaxed QK C-frag
//   IS W's A-fragment (order c0,c2,c1,c3).

#define VP 68   // smem V row pitch (floats)

__device__ float2 g_rope2[32 * 32];   // [row][j] = (cos,sin) for col pair 2j,2j+1

__global__ void rope_init_kernel() {
    int tdx = blockIdx.x * 32 + threadIdx.x;   // 0..1023
    int row = tdx >> 5;
    int j   = tdx & 31;                        // pair index
    const double ln1e4_over32 = 9.210340371976184 / 32.0;
    double th = exp(-(double)j * ln1e4_over32);   // theta_j = 10000^(-j/32)
    double s, c;
    sincos((double)row * th, &s, &c);
    g_rope2[tdx] = make_float2((float)c, (float)s);
}

__device__ __forceinline__ void split_tf32(float x, uint32_t &hi, uint32_t &lo) {
    float b;
    asm("cvt.rna.tf32.f32 %0, %1;" : "=f"(b) : "f"(x));
    hi = __float_as_uint(b);
    lo = __float_as_uint(x - b);
}

__device__ __forceinline__ void mma_tf32(float c[4], uint32_t a0, uint32_t a1,
                                         uint32_t a2, uint32_t a3,
                                         uint32_t b0, uint32_t b1) {
    asm("mma.sync.aligned.m16n8k8.row.col.f32.tf32.tf32.f32 "
        "{%0,%1,%2,%3}, {%4,%5,%6,%7}, {%8,%9}, {%0,%1,%2,%3};"
        : "+f"(c[0]), "+f"(c[1]), "+f"(c[2]), "+f"(c[3])
        : "r"(a0), "r"(a1), "r"(a2), "r"(a3), "r"(b0), "r"(b1));
}

// 3-pass split product accumulate: C += A*B with fp32-grade accuracy.
#define MMA3(Cacc, Ah, Al, B0h, B1h, B0l, B1l)                                   \
    do {                                                                         \
        mma_tf32(Cacc, Ah[0], Ah[1], Ah[2], Ah[3], B0h, B1h);                    \
        mma_tf32(Cacc, Al[0], Al[1], Al[2], Al[3], B0h, B1h);                    \
        mma_tf32(Cacc, Ah[0], Ah[1], Ah[2], Ah[3], B0l, B1l);                    \
    } while (0)

__global__ __launch_bounds__(32, 20)
void win_attn_kernel(const float* __restrict__ q,
                     const float* __restrict__ k,
                     const float* __restrict__ v,
                     float* __restrict__ out) {
    __shared__ __align__(16) float sV[32 * VP];   // 8704 B

    const uint32_t lane = threadIdx.x;
    const uint32_t g = lane >> 2;    // fragment group 0..7
    const uint32_t t = lane & 3u;    // thread-in-group 0..3
    const uint32_t job = blockIdx.x;            // 0..8191
    const uint32_t bh = job >> 6;               // b*16 + h
    const uint32_t jb = job & 63u;

    const uint32_t base = bh * (2048u * 64u) + jb * (32u * 64u);
    const float* Qb = q + base;
    const float* Kb = k + base;
    const float* Vb = v + base;

    // ---- kick off V GMEM->SMEM (completes during QK/softmax) ----
    {
        uint32_t sv;
        asm("{ .reg .u64 a; cvta.to.shared.u64 a, %1; cvt.u32.u64 %0, a; }"
            : "=r"(sv) : "l"(sV));
#pragma unroll
        for (int i = 0; i < 16; i++) {
            const uint32_t f = (uint32_t)i * 32u + lane;   // float4 index
            const uint32_t r = f >> 4, c4 = f & 15u;
            const float* src = Vb + r * 64u + c4 * 4u;
            uint32_t dst = sv + (r * VP + c4 * 4u) * 4u;
            asm volatile("cp.async.cg.shared.global [%0], [%1], 16;"
                         :: "r"(dst), "l"(src));
        }
        asm volatile("cp.async.commit_group;");
    }

    const float4* rope4 = (const float4*)g_rope2;   // [row*16 + slot]

    // ============ QK^T with causal pruning ============
    // m=0 (rows 0-15): key tiles nt 0,1 only. m=1 (rows 16-31): nt 0..3.
    float C0[2][4];          // m=0, nt 0..1
    float C1[4][4];          // m=1, nt 0..3
#pragma unroll
    for (int nt = 0; nt < 2; nt++)
#pragma unroll
        for (int j = 0; j < 4; j++) C0[nt][j] = 0.f;
#pragma unroll
    for (int nt = 0; nt < 4; nt++)
#pragma unroll
        for (int j = 0; j < 4; j++) C1[nt][j] = 0.f;

#pragma unroll
    for (int ktp = 0; ktp < 4; ktp++) {
        const uint32_t c0 = (uint32_t)ktp * 16u + 4u * t;  // 4 data cols
        const uint32_t ri = (uint32_t)ktp * 4u + t;        // rope slot

        // Rope rows {g, g+8, g+16, g+24} serve BOTH Q and K.
        float4 tt[4];
#pragma unroll
        for (int i = 0; i < 4; i++)
            tt[i] = rope4[((uint32_t)i * 8u + g) * 16u + ri];

        // rotated Q (RoPE + 0.125): m rows {m16+g, m16+g+8}
        float yq[2][2][4];
#pragma unroll
        for (int m = 0; m < 2; m++) {
            const uint32_t r0 = (uint32_t)m * 16u + g;
            float4 x0 = *(const float4*)(Qb + r0 * 64u + c0);
            float4 x1 = *(const float4*)(Qb + (r0 + 8u) * 64u + c0);
            float4 t0 = tt[2 * m];
            float4 t1 = tt[2 * m + 1];
            yq[m][0][0] = (x0.x * t0.x - x0.y * t0.y) * 0.125f;
            yq[m][0][1] = (x0.y * t0.x + x0.x * t0.y) * 0.125f;
            yq[m][0][2] = (x0.z * t0.z - x0.w * t0.w) * 0.125f;
            yq[m][0][3] = (x0.w * t0.z + x0.z * t0.w) * 0.125f;
            yq[m][1][0] = (x1.x * t1.x - x1.y * t1.y) * 0.125f;
            yq[m][1][1] = (x1.y * t1.x + x1.x * t1.y) * 0.125f;
            yq[m][1][2] = (x1.z * t1.z - x1.w * t1.w) * 0.125f;
            yq[m][1][3] = (x1.w * t1.z + x1.z * t1.w) * 0.125f;
        }
        // rotated K: rows nt8+g
        float yk[4][4];
#pragma unroll
        for (int nt = 0; nt < 4; nt++) {
            const uint32_t r = (uint32_t)nt * 8u + g;
            float4 x = *(const float4*)(Kb + r * 64u + c0);
            float4 tr = tt[nt];
            yk[nt][0] = x.x * tr.x - x.y * tr.y;
            yk[nt][1] = x.y * tr.x + x.x * tr.y;
            yk[nt][2] = x.z * tr.z - x.w * tr.w;
            yk[nt][3] = x.w * tr.z + x.z * tr.w;
        }

#pragma unroll
        for (int sub = 0; sub < 2; sub++) {
            uint32_t A0h[4], A0l[4], A1h[4], A1l[4];
            split_tf32(yq[0][0][2 * sub],     A0h[0], A0l[0]);
            split_tf32(yq[0][1][2 * sub],     A0h[1], A0l[1]);
            split_tf32(yq[0][0][2 * sub + 1], A0h[2], A0l[2]);
            split_tf32(yq[0][1][2 * sub + 1], A0h[3], A0l[3]);
            split_tf32(yq[1][0][2 * sub],     A1h[0], A1l[0]);
            split_tf32(yq[1][1][2 * sub],     A1h[1], A1l[1]);
            split_tf32(yq[1][0][2 * sub + 1], A1h[2], A1l[2]);
            split_tf32(yq[1][1][2 * sub + 1], A1h[3], A1l[3]);
#pragma unroll
            for (int nt = 0; nt < 4; nt++) {
                uint32_t Bh0, Bl0, Bh1, Bl1;
                split_tf32(yk[nt][2 * sub],     Bh0, Bl0);
                split_tf32(yk[nt][2 * sub + 1], Bh1, Bl1);
                if (nt < 2) MMA3(C0[nt], A0h, A0l, Bh0, Bh1, Bl0, Bl1);
                MMA3(C1[nt], A1h, A1l, Bh0, Bh1, Bl0, Bl1);
            }
        }
    }

    // ============ causal softmax ============
    // c0=(rA, 8nt+2t) c1=(rA,+1) c2=(rB,2t) c3=(rB,+1).
    {   // m = 0: rA = g, rB = g+8; tiles nt 0,1 only
        const int rA = (int)g, rB = rA + 8;
        float mxA = -1e30f, mxB = -1e30f;
#pragma unroll
        for (int nt = 0; nt < 2; nt++) {
            const int cc = 8 * nt + 2 * (int)t;
            if (cc     > rA) C0[nt][0] = -1e30f;
            if (cc + 1 > rA) C0[nt][1] = -1e30f;
            if (cc     > rB) C0[nt][2] = -1e30f;
            if (cc + 1 > rB) C0[nt][3] = -1e30f;
            mxA = fmaxf(mxA, fmaxf(C0[nt][0], C0[nt][1]));
            mxB = fmaxf(mxB, fmaxf(C0[nt][2], C0[nt][3]));
        }
        mxA = fmaxf(mxA, __shfl_xor_sync(0xffffffffu, mxA, 1));
        mxA = fmaxf(mxA, __shfl_xor_sync(0xffffffffu, mxA, 2));
        mxB = fmaxf(mxB, __shfl_xor_sync(0xffffffffu, mxB, 1));
        mxB = fmaxf(mxB, __shfl_xor_sync(0xffffffffu, mxB, 2));
        float sA = 0.f, sB = 0.f;
#pragma unroll
        for (int nt = 0; nt < 2; nt++) {
            C0[nt][0] = __expf(C0[nt][0] - mxA); sA += C0[nt][0];
            C0[nt][1] = __expf(C0[nt][1] - mxA); sA += C0[nt][1];
            C0[nt][2] = __expf(C0[nt][2] - mxB); sB += C0[nt][2];
            C0[nt][3] = __expf(C0[nt][3] - mxB); sB += C0[nt][3];
        }
        sA += __shfl_xor_sync(0xffffffffu, sA, 1);
        sA += __shfl_xor_sync(0xffffffffu, sA, 2);
        sB += __shfl_xor_sync(0xffffffffu, sB, 1);
        sB += __shfl_xor_sync(0xffffffffu, sB, 2);
        const float iA = 1.0f / sA, iB = 1.0f / sB;
#pragma unroll
        for (int nt = 0; nt < 2; nt++) {
            C0[nt][0] *= iA; C0[nt][1] *= iA;
            C0[nt][2] *= iB; C0[nt][3] *= iB;
        }
    }
    {   // m = 1: rA = 16+g, rB = 24+g; tiles nt 0..3
        const int rA = 16 + (int)g, rB = rA + 8;
        float mxA = -1e30f, mxB = -1e30f;
#pragma unroll
        for (int nt = 0; nt < 4; nt++) {
            const int cc = 8 * nt + 2 * (int)t;
            if (cc     > rA) C1[nt][0] = -1e30f;
            if (cc + 1 > rA) C1[nt][1] = -1e30f;
            if (cc     > rB) C1[nt][2] = -1e30f;
            if (cc + 1 > rB) C1[nt][3] = -1e30f;
            mxA = fmaxf(mxA, fmaxf(C1[nt][0], C1[nt][1]));
            mxB = fmaxf(mxB, fmaxf(C1[nt][2], C1[nt][3]));
        }
        mxA = fmaxf(mxA, __shfl_xor_sync(0xffffffffu, mxA, 1));
        mxA = fmaxf(mxA, __shfl_xor_sync(0xffffffffu, mxA, 2));
        mxB = fmaxf(mxB, __shfl_xor_sync(0xffffffffu, mxB, 1));
        mxB = fmaxf(mxB, __shfl_xor_sync(0xffffffffu, mxB, 2));
        float sA = 0.f, sB = 0.f;
#pragma unroll
        for (int nt = 0; nt < 4; nt++) {
            C1[nt][0] = __expf(C1[nt][0] - mxA); sA += C1[nt][0];
            C1[nt][1] = __expf(C1[nt][1] - mxA); sA += C1[nt][1];
            C1[nt][2] = __expf(C1[nt][2] - mxB); sB += C1[nt][2];
            C1[nt][3] = __expf(C1[nt][3] - mxB); sB += C1[nt][3];
        }
        sA += __shfl_xor_sync(0xffffffffu, sA, 1);
        sA += __shfl_xor_sync(0xffffffffu, sA, 2);
        sB += __shfl_xor_sync(0xffffffffu, sB, 1);
        sB += __shfl_xor_sync(0xffffffffu, sB, 2);
        const float iA = 1.0f / sA, iB = 1.0f / sB;
#pragma unroll
        for (int nt = 0; nt < 4; nt++) {
            C1[nt][0] *= iA; C1[nt][1] *= iA;
            C1[nt][2] *= iB; C1[nt][3] *= iB;
        }
    }

    // ---- V must be in smem now (overlapped with all of the above) ----
    asm volatile("cp.async.wait_group 0;");
    __syncwarp();

    // ============ O = W V with causal pruning ============
    // W A-frags == C frags (order c0,c2,c1,c3). m=0 uses kt 0,1 only.
    float* ob = out + (bh >> 4) * (2048u * 1024u) + jb * (32u * 1024u)
                    + (bh & 15u) * 64u;
#pragma unroll
    for (int half = 0; half < 2; half++) {
        float Cw0[4][4], Cw1[4][4];
#pragma unroll
        for (int nti = 0; nti < 4; nti++)
#pragma unroll
            for (int j = 0; j < 4; j++) { Cw0[nti][j] = 0.f; Cw1[nti][j] = 0.f; }

#pragma unroll
        for (int kt = 0; kt < 4; kt++) {
            uint32_t W1h[4], W1l[4];
            split_tf32(C1[kt][0], W1h[0], W1l[0]);
            split_tf32(C1[kt][2], W1h[1], W1l[1]);
            split_tf32(C1[kt][1], W1h[2], W1l[2]);
            split_tf32(C1[kt][3], W1h[3], W1l[3]);
            uint32_t W0h[4], W0l[4];
            if (kt < 2) {
                split_tf32(C0[kt][0], W0h[0], W0l[0]);
                split_tf32(C0[kt][2], W0h[1], W0l[1]);
                split_tf32(C0[kt][1], W0h[2], W0l[2]);
                split_tf32(C0[kt][3], W0h[3], W0l[3]);
            }
            const uint32_t p0 = (uint32_t)kt * 8u + 2u * t;   // permuted key rows
            const float* vr0 = &sV[p0 * VP];
            const float* vr1 = vr0 + VP;
#pragma unroll
            for (int nti = 0; nti < 4; nti++) {
                const uint32_t ncol = (uint32_t)(half * 4 + nti) * 8u + g;
                uint32_t b0h, b0l, b1h, b1l;
                split_tf32(vr0[ncol], b0h, b0l);
                split_tf32(vr1[ncol], b1h, b1l);
                if (kt < 2) MMA3(Cw0[nti], W0h, W0l, b0h, b1h, b0l, b1l);
                MMA3(Cw1[nti], W1h, W1l, b0h, b1h, b0l, b1l);
            }
        }

        // stores: m0 rows g/g+8, m1 rows 16+g/24+g; cols (half*4+nti)*8+2t
#pragma unroll
        for (int nti = 0; nti < 4; nti++) {
            const uint32_t cc = (uint32_t)(half * 4 + nti) * 8u + 2u * t;
            float* p0 = ob + g * 1024u + cc;
            *(float2*)p0               = make_float2(Cw0[nti][0], Cw0[nti][1]);
            *(float2*)(p0 + 8u * 1024u)  = make_float2(Cw0[nti][2], Cw0[nti][3]);
            float* p1 = ob + (16u + g) * 1024u + cc;
            *(float2*)p1               = make_float2(Cw1[nti][0], Cw1[nti][1]);
            *(float2*)(p1 + 8u * 1024u)  = make_float2(Cw1[nti][2], Cw1[nti][3]);
        }
    }
}

extern "C" void kernel_launch(void* const* d_in, const int* in_sizes, int n_in,
                              void* d_out, int out_size) {
    const float* q = (const float*)d_in[0];
    const float* k = (const float*)d_in[1];
    const float* v = (const float*)d_in[2];
    float* out = (float*)d_out;

    rope_init_kernel<<<32, 32>>>();
    win_attn_kernel<<<8 * 16 * 64, 32>>>(q, k, v, out);
}